// round 1
// baseline (speedup 1.0000x reference)
#include <cuda_runtime.h>
#include <math.h>

// Problem constants (fixed by the dataset)
#define T_TOK   2048          // B*S tokens
#define H_DIM   1024
#define N_EXP   16
#define F_DIM   1024
#define GU_N    2048          // 2*F
#define N_SLOTS (T_TOK * 2)   // top-2 => 4096 slots

// ---------------- device scratch (no allocations allowed) ----------------
__device__ float g_gu[(size_t)N_SLOTS * GU_N];      // [slot, 2F]  32 MB
__device__ float g_gated[(size_t)N_SLOTS * F_DIM];  // [slot, F]   16 MB
__device__ float g_eo[(size_t)N_SLOTS * H_DIM];     // [slot, H]   16 MB
__device__ int   g_cnt[N_EXP];
__device__ int   g_slots[N_EXP * N_SLOTS];          // slot ids per expert bucket
__device__ float g_w[N_SLOTS];                      // routing weight per slot

// ---------------- kernel 0: zero counters ----------------
__global__ void zero_cnt_kernel() {
    if (threadIdx.x < N_EXP) g_cnt[threadIdx.x] = 0;
}

// ---------------- kernel 1: router (one warp per token) ----------------
__global__ void router_kernel(const float* __restrict__ x,
                              const float* __restrict__ rw) {
    int t = blockIdx.x * blockDim.y + threadIdx.y;
    if (t >= T_TOK) return;
    int lane = threadIdx.x;

    float acc[N_EXP];
#pragma unroll
    for (int e = 0; e < N_EXP; e++) acc[e] = 0.f;

    const float* xrow = x + (size_t)t * H_DIM;
    for (int h = lane; h < H_DIM; h += 32) {
        float xv = xrow[h];
        const float4* r4 = (const float4*)(rw + (size_t)h * N_EXP);
#pragma unroll
        for (int q = 0; q < 4; q++) {
            float4 v = r4[q];
            acc[q * 4 + 0] += xv * v.x;
            acc[q * 4 + 1] += xv * v.y;
            acc[q * 4 + 2] += xv * v.z;
            acc[q * 4 + 3] += xv * v.w;
        }
    }
#pragma unroll
    for (int e = 0; e < N_EXP; e++) {
#pragma unroll
        for (int off = 16; off > 0; off >>= 1)
            acc[e] += __shfl_down_sync(0xffffffffu, acc[e], off);
    }
    if (lane == 0) {
        int i0 = -1, i1 = -1;
        float v0 = -INFINITY, v1 = -INFINITY;
#pragma unroll
        for (int e = 0; e < N_EXP; e++) {
            float v = acc[e];
            if (v > v0) { v1 = v0; i1 = i0; v0 = v; i0 = e; }
            else if (v > v1) { v1 = v; i1 = e; }
        }
        // softmax over the 2 top values (v0 >= v1)
        float w0 = 1.f / (1.f + expf(v1 - v0));
        float w1 = 1.f - w0;

        int p0 = atomicAdd(&g_cnt[i0], 1);
        g_slots[i0 * N_SLOTS + p0] = 2 * t;
        g_w[2 * t] = w0;
        int p1 = atomicAdd(&g_cnt[i1], 1);
        g_slots[i1 * N_SLOTS + p1] = 2 * t + 1;
        g_w[2 * t + 1] = w1;
    }
}

// ---------------- tiled gathered SGEMM (64x64x16, 4x4/thread) ----------------
#define TM 64
#define TN 64
#define TK 16

// C[slot, n0+j] = sum_k A[tok(slot), k] * W[e][k][n]   (gate_up)
__global__ void gateup_kernel(const float* __restrict__ x,
                              const float* __restrict__ wgu) {
    int e = blockIdx.y;
    int cnt = g_cnt[e];
    int m0 = blockIdx.x * TM;
    if (m0 >= cnt) return;
    int n0 = blockIdx.z * TN;

    __shared__ float As[TK][TM + 1];
    __shared__ float Bs[TK][TN];
    __shared__ int rows[TM];   // slot id per local row, -1 if invalid

    int tid = threadIdx.x;
    if (tid < TM) {
        int m = m0 + tid;
        rows[tid] = (m < cnt) ? g_slots[e * N_SLOTS + m] : -1;
    }
    __syncthreads();

    float c[4][4] = {};
    int tx = tid & 15, ty = tid >> 4;
    const float* wbase = wgu + (size_t)e * H_DIM * GU_N;

    for (int k0 = 0; k0 < H_DIM; k0 += TK) {
#pragma unroll
        for (int i = 0; i < 4; i++) {
            int idx = tid + i * 256;
            int k = idx & 15, m = idx >> 4;
            int s = rows[m];
            As[k][m] = (s >= 0) ? x[(size_t)(s >> 1) * H_DIM + k0 + k] : 0.f;
        }
#pragma unroll
        for (int i = 0; i < 4; i++) {
            int idx = tid + i * 256;
            int n = idx & 63, k = idx >> 6;
            Bs[k][n] = wbase[(size_t)(k0 + k) * GU_N + n0 + n];
        }
        __syncthreads();
#pragma unroll
        for (int k = 0; k < TK; k++) {
            float a[4], b[4];
#pragma unroll
            for (int i = 0; i < 4; i++) a[i] = As[k][ty * 4 + i];
#pragma unroll
            for (int j = 0; j < 4; j++) b[j] = Bs[k][tx * 4 + j];
#pragma unroll
            for (int i = 0; i < 4; i++)
#pragma unroll
                for (int j = 0; j < 4; j++)
                    c[i][j] += a[i] * b[j];
        }
        __syncthreads();
    }
#pragma unroll
    for (int i = 0; i < 4; i++) {
        int m = m0 + ty * 4 + i;
        if (m < cnt) {
            int s = g_slots[e * N_SLOTS + m];
            float* orow = g_gu + (size_t)s * GU_N + n0 + tx * 4;
#pragma unroll
            for (int j = 0; j < 4; j++) orow[j] = c[i][j];
        }
    }
}

// ---------------- kernel 3: SiLU-gate ----------------
__global__ void silu_kernel() {
    int idx = blockIdx.x * blockDim.x + threadIdx.x;
    if (idx >= N_SLOTS * F_DIM) return;
    int s = idx >> 10;          // F_DIM = 1024
    int f = idx & 1023;
    float g = g_gu[(size_t)s * GU_N + f];
    float u = g_gu[(size_t)s * GU_N + F_DIM + f];
    g_gated[idx] = (g / (1.f + expf(-g))) * u;
}

// ---------------- kernel 4: down-proj GEMM (with routing weight) ----------------
__global__ void down_kernel(const float* __restrict__ wd) {
    int e = blockIdx.y;
    int cnt = g_cnt[e];
    int m0 = blockIdx.x * TM;
    if (m0 >= cnt) return;
    int n0 = blockIdx.z * TN;

    __shared__ float As[TK][TM + 1];
    __shared__ float Bs[TK][TN];
    __shared__ int rows[TM];

    int tid = threadIdx.x;
    if (tid < TM) {
        int m = m0 + tid;
        rows[tid] = (m < cnt) ? g_slots[e * N_SLOTS + m] : -1;
    }
    __syncthreads();

    float c[4][4] = {};
    int tx = tid & 15, ty = tid >> 4;
    const float* wbase = wd + (size_t)e * F_DIM * H_DIM;

    for (int k0 = 0; k0 < F_DIM; k0 += TK) {
#pragma unroll
        for (int i = 0; i < 4; i++) {
            int idx = tid + i * 256;
            int k = idx & 15, m = idx >> 4;
            int s = rows[m];
            As[k][m] = (s >= 0) ? g_gated[(size_t)s * F_DIM + k0 + k] : 0.f;
        }
#pragma unroll
        for (int i = 0; i < 4; i++) {
            int idx = tid + i * 256;
            int n = idx & 63, k = idx >> 6;
            Bs[k][n] = wbase[(size_t)(k0 + k) * H_DIM + n0 + n];
        }
        __syncthreads();
#pragma unroll
        for (int k = 0; k < TK; k++) {
            float a[4], b[4];
#pragma unroll
            for (int i = 0; i < 4; i++) a[i] = As[k][ty * 4 + i];
#pragma unroll
            for (int j = 0; j < 4; j++) b[j] = Bs[k][tx * 4 + j];
#pragma unroll
            for (int i = 0; i < 4; i++)
#pragma unroll
                for (int j = 0; j < 4; j++)
                    c[i][j] += a[i] * b[j];
        }
        __syncthreads();
    }
#pragma unroll
    for (int i = 0; i < 4; i++) {
        int m = m0 + ty * 4 + i;
        if (m < cnt) {
            int s = g_slots[e * N_SLOTS + m];
            float w = g_w[s];
            float* orow = g_eo + (size_t)s * H_DIM + n0 + tx * 4;
#pragma unroll
            for (int j = 0; j < 4; j++) orow[j] = w * c[i][j];
        }
    }
}

// ---------------- kernel 5: combine the 2 slots of each token ----------------
__global__ void combine_kernel(float* __restrict__ out) {
    int idx = blockIdx.x * blockDim.x + threadIdx.x;
    if (idx >= T_TOK * H_DIM) return;
    int t = idx >> 10;          // H_DIM = 1024
    int h = idx & 1023;
    out[idx] = g_eo[(size_t)(2 * t) * H_DIM + h] +
               g_eo[(size_t)(2 * t + 1) * H_DIM + h];
}

// ---------------- launch ----------------
extern "C" void kernel_launch(void* const* d_in, const int* in_sizes, int n_in,
                              void* d_out, int out_size) {
    const float* hidden = (const float*)d_in[0];   // [2,1024,1024]
    const float* router = (const float*)d_in[1];   // [1024,16]
    const float* w_gu   = (const float*)d_in[2];   // [16,1024,2048]
    const float* w_dn   = (const float*)d_in[3];   // [16,1024,1024]
    float* out = (float*)d_out;                    // [2,1024,1024]

    zero_cnt_kernel<<<1, 32>>>();

    dim3 rblk(32, 8);
    router_kernel<<<T_TOK / 8, rblk>>>(hidden, router);

    dim3 gu_grid(N_SLOTS / TM, N_EXP, GU_N / TN);   // 64 x 16 x 32
    gateup_kernel<<<gu_grid, 256>>>(hidden, w_gu);

    silu_kernel<<<(N_SLOTS * F_DIM + 255) / 256, 256>>>();

    dim3 dn_grid(N_SLOTS / TM, N_EXP, H_DIM / TN);  // 64 x 16 x 16
    down_kernel<<<dn_grid, 256>>>(w_dn);

    combine_kernel<<<(T_TOK * H_DIM + 255) / 256, 256>>>(out);
}

// round 2
// speedup vs baseline: 1.0010x; 1.0010x over previous
#include <cuda_runtime.h>
#include <math.h>

// Problem constants (fixed by the dataset)
#define T_TOK   2048          // B*S tokens
#define H_DIM   1024
#define N_EXP   16
#define F_DIM   1024
#define GU_N    2048          // 2*F
#define N_SLOTS (T_TOK * 2)   // top-2 => 4096 slots

// ---------------- device scratch (no allocations allowed) ----------------
__device__ float g_gu[(size_t)N_SLOTS * GU_N];      // [slot, 2F]  32 MB
__device__ float g_gated[(size_t)N_SLOTS * F_DIM];  // [slot, F]   16 MB
__device__ float g_eo[(size_t)N_SLOTS * H_DIM];     // [slot, H]   16 MB
__device__ int   g_cnt[N_EXP];
__device__ int   g_slots[N_EXP * N_SLOTS];          // slot ids per expert bucket
__device__ float g_w[N_SLOTS];                      // routing weight per slot

// ---------------- kernel 0: zero counters ----------------
__global__ void zero_cnt_kernel() {
    if (threadIdx.x < N_EXP) g_cnt[threadIdx.x] = 0;
}

// ---------------- kernel 1: router (one warp per token) ----------------
__global__ void router_kernel(const float* __restrict__ x,
                              const float* __restrict__ rw) {
    int t = blockIdx.x * blockDim.y + threadIdx.y;
    if (t >= T_TOK) return;
    int lane = threadIdx.x;

    float acc[N_EXP];
#pragma unroll
    for (int e = 0; e < N_EXP; e++) acc[e] = 0.f;

    const float* xrow = x + (size_t)t * H_DIM;
    for (int h = lane; h < H_DIM; h += 32) {
        float xv = xrow[h];
        const float4* r4 = (const float4*)(rw + (size_t)h * N_EXP);
#pragma unroll
        for (int q = 0; q < 4; q++) {
            float4 v = r4[q];
            acc[q * 4 + 0] += xv * v.x;
            acc[q * 4 + 1] += xv * v.y;
            acc[q * 4 + 2] += xv * v.z;
            acc[q * 4 + 3] += xv * v.w;
        }
    }
#pragma unroll
    for (int e = 0; e < N_EXP; e++) {
#pragma unroll
        for (int off = 16; off > 0; off >>= 1)
            acc[e] += __shfl_down_sync(0xffffffffu, acc[e], off);
    }
    if (lane == 0) {
        int i0 = -1, i1 = -1;
        float v0 = -INFINITY, v1 = -INFINITY;
#pragma unroll
        for (int e = 0; e < N_EXP; e++) {
            float v = acc[e];
            if (v > v0) { v1 = v0; i1 = i0; v0 = v; i0 = e; }
            else if (v > v1) { v1 = v; i1 = e; }
        }
        // softmax over the 2 top values (v0 >= v1)
        float w0 = 1.f / (1.f + expf(v1 - v0));
        float w1 = 1.f - w0;

        int p0 = atomicAdd(&g_cnt[i0], 1);
        g_slots[i0 * N_SLOTS + p0] = 2 * t;
        g_w[2 * t] = w0;
        int p1 = atomicAdd(&g_cnt[i1], 1);
        g_slots[i1 * N_SLOTS + p1] = 2 * t + 1;
        g_w[2 * t + 1] = w1;
    }
}

// ---------------- tiled gathered SGEMM (64x64x16, 4x4/thread) ----------------
#define TM 64
#define TN 64
#define TK 16

// C[slot, n0+j] = sum_k A[tok(slot), k] * W[e][k][n]   (gate_up)
__global__ void gateup_kernel(const float* __restrict__ x,
                              const float* __restrict__ wgu) {
    int e = blockIdx.y;
    int cnt = g_cnt[e];
    int m0 = blockIdx.x * TM;
    if (m0 >= cnt) return;
    int n0 = blockIdx.z * TN;

    __shared__ float As[TK][TM + 1];
    __shared__ float Bs[TK][TN];
    __shared__ int rows[TM];   // slot id per local row, -1 if invalid

    int tid = threadIdx.x;
    if (tid < TM) {
        int m = m0 + tid;
        rows[tid] = (m < cnt) ? g_slots[e * N_SLOTS + m] : -1;
    }
    __syncthreads();

    float c[4][4] = {};
    int tx = tid & 15, ty = tid >> 4;
    const float* wbase = wgu + (size_t)e * H_DIM * GU_N;

    for (int k0 = 0; k0 < H_DIM; k0 += TK) {
#pragma unroll
        for (int i = 0; i < 4; i++) {
            int idx = tid + i * 256;
            int k = idx & 15, m = idx >> 4;
            int s = rows[m];
            As[k][m] = (s >= 0) ? x[(size_t)(s >> 1) * H_DIM + k0 + k] : 0.f;
        }
#pragma unroll
        for (int i = 0; i < 4; i++) {
            int idx = tid + i * 256;
            int n = idx & 63, k = idx >> 6;
            Bs[k][n] = wbase[(size_t)(k0 + k) * GU_N + n0 + n];
        }
        __syncthreads();
#pragma unroll
        for (int k = 0; k < TK; k++) {
            float a[4], b[4];
#pragma unroll
            for (int i = 0; i < 4; i++) a[i] = As[k][ty * 4 + i];
#pragma unroll
            for (int j = 0; j < 4; j++) b[j] = Bs[k][tx * 4 + j];
#pragma unroll
            for (int i = 0; i < 4; i++)
#pragma unroll
                for (int j = 0; j < 4; j++)
                    c[i][j] += a[i] * b[j];
        }
        __syncthreads();
    }
#pragma unroll
    for (int i = 0; i < 4; i++) {
        int m = m0 + ty * 4 + i;
        if (m < cnt) {
            int s = g_slots[e * N_SLOTS + m];
            float* orow = g_gu + (size_t)s * GU_N + n0 + tx * 4;
#pragma unroll
            for (int j = 0; j < 4; j++) orow[j] = c[i][j];
        }
    }
}

// ---------------- kernel 3: SiLU-gate ----------------
__global__ void silu_kernel() {
    int idx = blockIdx.x * blockDim.x + threadIdx.x;
    if (idx >= N_SLOTS * F_DIM) return;
    int s = idx >> 10;          // F_DIM = 1024
    int f = idx & 1023;
    float g = g_gu[(size_t)s * GU_N + f];
    float u = g_gu[(size_t)s * GU_N + F_DIM + f];
    g_gated[idx] = (g / (1.f + expf(-g))) * u;
}

// ---------------- kernel 4: down-proj GEMM (with routing weight) ----------------
__global__ void down_kernel(const float* __restrict__ wd) {
    int e = blockIdx.y;
    int cnt = g_cnt[e];
    int m0 = blockIdx.x * TM;
    if (m0 >= cnt) return;
    int n0 = blockIdx.z * TN;

    __shared__ float As[TK][TM + 1];
    __shared__ float Bs[TK][TN];
    __shared__ int rows[TM];

    int tid = threadIdx.x;
    if (tid < TM) {
        int m = m0 + tid;
        rows[tid] = (m < cnt) ? g_slots[e * N_SLOTS + m] : -1;
    }
    __syncthreads();

    float c[4][4] = {};
    int tx = tid & 15, ty = tid >> 4;
    const float* wbase = wd + (size_t)e * F_DIM * H_DIM;

    for (int k0 = 0; k0 < F_DIM; k0 += TK) {
#pragma unroll
        for (int i = 0; i < 4; i++) {
            int idx = tid + i * 256;
            int k = idx & 15, m = idx >> 4;
            int s = rows[m];
            As[k][m] = (s >= 0) ? g_gated[(size_t)s * F_DIM + k0 + k] : 0.f;
        }
#pragma unroll
        for (int i = 0; i < 4; i++) {
            int idx = tid + i * 256;
            int n = idx & 63, k = idx >> 6;
            Bs[k][n] = wbase[(size_t)(k0 + k) * H_DIM + n0 + n];
        }
        __syncthreads();
#pragma unroll
        for (int k = 0; k < TK; k++) {
            float a[4], b[4];
#pragma unroll
            for (int i = 0; i < 4; i++) a[i] = As[k][ty * 4 + i];
#pragma unroll
            for (int j = 0; j < 4; j++) b[j] = Bs[k][tx * 4 + j];
#pragma unroll
            for (int i = 0; i < 4; i++)
#pragma unroll
                for (int j = 0; j < 4; j++)
                    c[i][j] += a[i] * b[j];
        }
        __syncthreads();
    }
#pragma unroll
    for (int i = 0; i < 4; i++) {
        int m = m0 + ty * 4 + i;
        if (m < cnt) {
            int s = g_slots[e * N_SLOTS + m];
            float w = g_w[s];
            float* orow = g_eo + (size_t)s * H_DIM + n0 + tx * 4;
#pragma unroll
            for (int j = 0; j < 4; j++) orow[j] = w * c[i][j];
        }
    }
}

// ---------------- kernel 5: combine the 2 slots of each token ----------------
__global__ void combine_kernel(float* __restrict__ out) {
    int idx = blockIdx.x * blockDim.x + threadIdx.x;
    if (idx >= T_TOK * H_DIM) return;
    int t = idx >> 10;          // H_DIM = 1024
    int h = idx & 1023;
    out[idx] = g_eo[(size_t)(2 * t) * H_DIM + h] +
               g_eo[(size_t)(2 * t + 1) * H_DIM + h];
}

// ---------------- launch ----------------
extern "C" void kernel_launch(void* const* d_in, const int* in_sizes, int n_in,
                              void* d_out, int out_size) {
    const float* hidden = (const float*)d_in[0];   // [2,1024,1024]
    const float* router = (const float*)d_in[1];   // [1024,16]
    const float* w_gu   = (const float*)d_in[2];   // [16,1024,2048]
    const float* w_dn   = (const float*)d_in[3];   // [16,1024,1024]
    float* out = (float*)d_out;                    // [2,1024,1024]

    zero_cnt_kernel<<<1, 32>>>();

    dim3 rblk(32, 8);
    router_kernel<<<T_TOK / 8, rblk>>>(hidden, router);

    dim3 gu_grid(N_SLOTS / TM, N_EXP, GU_N / TN);   // 64 x 16 x 32
    gateup_kernel<<<gu_grid, 256>>>(hidden, w_gu);

    silu_kernel<<<(N_SLOTS * F_DIM + 255) / 256, 256>>>();

    dim3 dn_grid(N_SLOTS / TM, N_EXP, H_DIM / TN);  // 64 x 16 x 16
    down_kernel<<<dn_grid, 256>>>(w_dn);

    combine_kernel<<<(T_TOK * H_DIM + 255) / 256, 256>>>(out);
}